// round 13
// baseline (speedup 1.0000x reference)
#include <cuda_runtime.h>
#include <cuda_fp16.h>
#include <mma.h>
#include <cstdint>
#include <math.h>

using namespace nvcuda;

#define NMAX 100000
#define EMAX 800000
#define CDIM 128
#define KDIM 256

#define BETA_F 0.6931471805599453f
#define C1_F   0.15342640972002733f

// ---------------- scratch ----------------------------------------------------
__device__ int    g_count[NMAX];
__device__ float  g_dis[NMAX];
__device__ int    g_rowstart[NMAX];
__device__ int    g_cursor[NMAX];
__device__ int    g_csr[EMAX];
__device__ int    g_state[512];                // 0=invalid 1=aggregate 2=prefix
__device__ int    g_agg[512];
__device__ int    g_pre[512];
__device__ __half g_xh[(size_t)NMAX * CDIM];   // fp16 mirror of x (gather src)
__device__ __half g_x0h[(size_t)NMAX * CDIM];  // fp16 mirror of x0 (GEMM A)
__device__ __half g_hh[(size_t)NMAX * CDIM];   // h in fp16 (GEMM A)
__device__ __half g_bth[KDIM * CDIM];          // B' = beta*W + C1*[I;I], fp16

// ---------------- helpers ----------------------------------------------------
__device__ __forceinline__ uint32_t cvta_s(const void* p) {
    uint32_t a;
    asm("{ .reg .u64 t; cvta.to.shared.u64 t, %1; cvt.u32.u64 %0, t; }"
        : "=r"(a) : "l"(p));
    return a;
}

__device__ __forceinline__ void cp_async16(uint32_t dst, const void* src,
                                           uint32_t src_bytes) {
    asm volatile("cp.async.ca.shared.global [%0], [%1], 16, %2;"
                 :: "r"(dst), "l"(src), "r"(src_bytes) : "memory");
}

__device__ __forceinline__ void accum8(float* acc, uint4 r, float w) {
    __half2* hp = (__half2*)&r;
#pragma unroll
    for (int q = 0; q < 4; ++q) {
        float2 f = __half22float2(hp[q]);
        acc[2 * q]     += w * f.x;
        acc[2 * q + 1] += w * f.y;
    }
}

// ---------------- prep (fused): counts/state zero + B' + fp16 mirrors --------
__global__ void k_prep(const float* __restrict__ x, const float* __restrict__ x0,
                       const float* __restrict__ w1, const float* __restrict__ w2,
                       int n, int t4) {
    int i = blockIdx.x * blockDim.x + threadIdx.x;
    if (i < n) g_count[i] = 0;
    if (i < 512) g_state[i] = 0;
    if (i < KDIM * CDIM) {
        int nn = i & 127;
        int kk = i >> 7;
        float v = (kk < 128) ? w1[kk * 128 + nn] : w2[(kk - 128) * 128 + nn];
        float b = BETA_F * v;
        if ((kk & 127) == nn) b += C1_F;         // fold C1*(h+x0) into GEMM
        g_bth[i] = __float2half(b);
    }
    const float* src;
    __half* dst;
    int idx;
    if (i < t4)          { src = x;  dst = g_xh;  idx = i; }
    else if (i < 2 * t4) { src = x0; dst = g_x0h; idx = i - t4; }
    else return;
    float4 v = ((const float4*)src)[idx];
    __half2 a = __floats2half2_rn(v.x, v.y);
    __half2 b = __floats2half2_rn(v.z, v.w);
    uint2 pk;
    pk.x = *(uint32_t*)&a;
    pk.y = *(uint32_t*)&b;
    ((uint2*)dst)[idx] = pk;
}

__global__ void k_degree(const int* __restrict__ ei, int e) {
    int i = blockIdx.x * blockDim.x + threadIdx.x;
    if (i < e) atomicAdd(&g_count[ei[e + i]], 1);
}

// ---------------- single-pass scan (decoupled lookback) ----------------------
// dis + block scan + cross-block prefix + rowstart/cursor, one kernel.
__global__ void k_scan(int n) {
    __shared__ int sm[256];
    __shared__ int s_base;
    int t = threadIdx.x;
    int b = blockIdx.x;
    int i = b * 256 + t;
    int c = (i < n) ? g_count[i] : 0;
    if (i < n) g_dis[i] = rsqrtf((float)(c + 1));
    sm[t] = c;
    __syncthreads();
    for (int off = 1; off < 256; off <<= 1) {
        int v = (t >= off) ? sm[t - off] : 0;
        __syncthreads();
        sm[t] += v;
        __syncthreads();
    }
    if (t == 0) {
        int total = sm[255];
        if (b == 0) {
            g_pre[0] = total;
            __threadfence();
            g_state[0] = 2;
            s_base = 0;
        } else {
            g_agg[b] = total;
            __threadfence();
            g_state[b] = 1;
            int base = 0;
            int p = b - 1;
            while (true) {
                int st;
                do { st = *(volatile int*)&g_state[p]; } while (st == 0);
                __threadfence();
                if (st == 2) { base += g_pre[p]; break; }
                base += g_agg[p];
                --p;
            }
            g_pre[b] = base + total;
            __threadfence();
            g_state[b] = 2;
            s_base = base;
        }
    }
    __syncthreads();
    if (i < n) {
        int excl = s_base + sm[t] - c;
        g_rowstart[i] = excl;
        g_cursor[i]   = excl;
    }
}

__global__ void k_fill(const int* __restrict__ ei, int e) {
    int i = blockIdx.x * blockDim.x + threadIdx.x;
    if (i < e) {
        int s = ei[i];
        int d = ei[e + i];
        int pos = atomicAdd(&g_cursor[d], 1);
        g_csr[pos] = s;
    }
}

// ---------------- gather SpMM: warp = node, 2x16-lane groups, LDG.128 --------
__global__ void k_spmm(int n, int e) {
    int warp = (blockIdx.x * blockDim.x + threadIdx.x) >> 5;
    if (warp >= n) return;
    int lane = threadIdx.x & 31;
    int sub  = lane >> 4;          // edge-parity group 0/1
    int off  = lane & 15;          // 16B chunk within the 256B row

    const uint4* xr = (const uint4*)g_xh;   // row stride = 16 uint4

    float di = g_dis[warp];
    float acc[8];
#pragma unroll
    for (int q = 0; q < 8; ++q) acc[q] = 0.f;

    if (sub == 0) {                // self-loop on group 0
        uint4 r = xr[(size_t)warp * 16 + off];
        accum8(acc, r, di * di);
    }

    int j   = g_rowstart[warp] + sub;
    int end = (warp + 1 < n) ? g_rowstart[warp + 1] : e;

    for (; j + 2 < end; j += 4) {  // 2 edges per group per iter (4/warp)
        int i0 = __ldg(&g_csr[j]);
        int i1 = __ldg(&g_csr[j + 2]);
        float w0 = di * __ldg(&g_dis[i0]);
        float w1 = di * __ldg(&g_dis[i1]);
        uint4 r0 = xr[(size_t)i0 * 16 + off];
        uint4 r1 = xr[(size_t)i1 * 16 + off];
        accum8(acc, r0, w0);
        accum8(acc, r1, w1);
    }
    if (j < end) {
        int i0 = __ldg(&g_csr[j]);
        float w0 = di * __ldg(&g_dis[i0]);
        uint4 r0 = xr[(size_t)i0 * 16 + off];
        accum8(acc, r0, w0);
    }

    // merge the two edge-parity groups
#pragma unroll
    for (int q = 0; q < 8; ++q)
        acc[q] += __shfl_down_sync(0xFFFFFFFF, acc[q], 16);

    if (sub == 0) {
        __half2 o[4];
#pragma unroll
        for (int q = 0; q < 4; ++q)
            o[q] = __floats2half2_rn(acc[2 * q], acc[2 * q + 1]);
        ((uint4*)g_hh)[(size_t)warp * 16 + off] = *(uint4*)o;
    }
}

// ---------------- fp16 WMMA GEMM (m16n16k16), cp.async double-buffered -------
// out = relu( [h|x0] @ g_bth ),  [N,256]x[256,128]; C1 term folded into g_bth
#define BM 128
#define BN 128
#define BK 64
#define LDA 72      // halfs (144 B pitch)
#define LDB 136     // halfs (272 B pitch)
#define NT 4

#define STG_A (128 * 72 * 2)   // 18432 B
#define STG_B (64 * 136 * 2)   // 17408 B
#define STG   (STG_A + STG_B)  // 35840 B
#define GSMEM_BYTES (2 * STG)  // 71680 B (boundary-block C park reuses this)

__global__ __launch_bounds__(256)
void k_gemm(float* __restrict__ out, int n) {
    extern __shared__ char smemc[];
    uint32_t sbase = cvta_s(smemc);

    int tid  = threadIdx.x;
    int warp = tid >> 5;
    int bm   = blockIdx.x * BM;
    int wm   = (warp >> 1) * 32;      // 0,32,64,96
    int wn   = (warp & 1) * 64;       // 0,64

    int ar  = tid >> 3;               // 0..31
    int ac8 = (tid & 7) * 8;          // half offset 0..56

    wmma::fragment<wmma::accumulator, 16, 16, 16, float> c[2][4];
#pragma unroll
    for (int i = 0; i < 2; ++i)
#pragma unroll
        for (int jf = 0; jf < 4; ++jf) wmma::fill_fragment(c[i][jf], 0.0f);

    auto issue_stage = [&](int s, int kt) {
        uint32_t aB = sbase + s * STG;
        uint32_t bB = aB + STG_A;
        const __half* Ap = (kt < 2) ? g_hh : g_x0h;
        int k0 = (kt & 1) * 64;
#pragma unroll
        for (int q = 0; q < 4; ++q) {
            int r  = ar + 32 * q;
            int gi = bm + r;
            const __half* src = Ap + (size_t)gi * CDIM + k0 + ac8;
            cp_async16(aB + (uint32_t)(r * LDA + ac8) * 2, src,
                       (gi < n) ? 16u : 0u);
            int idx = tid + 256 * q;
            int kb  = idx >> 4;            // 0..63
            int bc8 = (idx & 15) * 8;      // 0..120
            const __half* bsrc = g_bth + (size_t)(kt * 64 + kb) * CDIM + bc8;
            cp_async16(bB + (uint32_t)(kb * LDB + bc8) * 2, bsrc, 16u);
        }
        asm volatile("cp.async.commit_group;" ::: "memory");
    };

    issue_stage(0, 0);

    // deliberately NOT unrolled (L0 I$; R4/R10-proven)
    for (int kt = 0; kt < NT; ++kt) {
        if (kt + 1 < NT) {
            issue_stage((kt + 1) & 1, kt + 1);
            asm volatile("cp.async.wait_group 1;" ::: "memory");
        } else {
            asm volatile("cp.async.wait_group 0;" ::: "memory");
        }
        __syncthreads();

        const __half* sA = (const __half*)(smemc + (kt & 1) * STG);
        const __half* sB = (const __half*)(smemc + (kt & 1) * STG + STG_A);

#pragma unroll
        for (int kk = 0; kk < BK; kk += 16) {
            wmma::fragment<wmma::matrix_a, 16, 16, 16, __half,
                           wmma::row_major> af[2];
            wmma::fragment<wmma::matrix_b, 16, 16, 16, __half,
                           wmma::row_major> bf[4];
#pragma unroll
            for (int i = 0; i < 2; ++i)
                wmma::load_matrix_sync(af[i], &sA[(wm + 16 * i) * LDA + kk], LDA);
#pragma unroll
            for (int jf = 0; jf < 4; ++jf)
                wmma::load_matrix_sync(bf[jf], &sB[kk * LDB + wn + 16 * jf], LDB);
#pragma unroll
            for (int i = 0; i < 2; ++i)
#pragma unroll
                for (int jf = 0; jf < 4; ++jf)
                    wmma::mma_sync(c[i][jf], af[i], bf[jf], c[i][jf]);
        }
        __syncthreads();
    }

    // fragment-level relu
#pragma unroll
    for (int i = 0; i < 2; ++i)
#pragma unroll
        for (int jf = 0; jf < 4; ++jf)
#pragma unroll
            for (int t = 0; t < c[i][jf].num_elements; ++t)
                c[i][jf].x[t] = fmaxf(c[i][jf].x[t], 0.f);

    if (bm + BM <= n) {
        // interior block: store fragments straight to gmem (no smem park)
#pragma unroll
        for (int i = 0; i < 2; ++i)
#pragma unroll
            for (int jf = 0; jf < 4; ++jf)
                wmma::store_matrix_sync(
                    out + (size_t)(bm + wm + 16 * i) * CDIM + wn + 16 * jf,
                    c[i][jf], CDIM, wmma::mem_row_major);
    } else {
        // boundary block: park in smem, masked store
        float* sC = (float*)smemc;
#pragma unroll
        for (int i = 0; i < 2; ++i)
#pragma unroll
            for (int jf = 0; jf < 4; ++jf)
                wmma::store_matrix_sync(&sC[(wm + 16 * i) * 128 + wn + 16 * jf],
                                        c[i][jf], 128, wmma::mem_row_major);
        __syncthreads();
        for (int idx = tid; idx < BM * 32; idx += 256) {
            int r  = idx >> 5;
            int c4 = (idx & 31) * 4;
            int gi = bm + r;
            if (gi < n) {
                float4 g = *(float4*)&sC[r * 128 + c4];
                *(float4*)(out + (size_t)gi * CDIM + c4) = g;
            }
        }
    }
}

// ---------------- launch -----------------------------------------------------
extern "C" void kernel_launch(void* const* d_in, const int* in_sizes, int n_in,
                              void* d_out, int out_size) {
    const float* x  = (const float*)d_in[0];
    const float* x0 = (const float*)d_in[1];
    const float* w1 = (const float*)d_in[2];
    const float* w2 = (const float*)d_in[3];
    const int*   ei = (const int*)d_in[4];
    float* out = (float*)d_out;

    int n = in_sizes[0] / CDIM;
    int e = in_sizes[4] / 2;
    int nb = (n + 255) / 256;
    int eb = (e + 255) / 256;
    int t4 = n * (CDIM / 4);          // float4 count per feature matrix

    static int attr_set = 0;
    if (!attr_set) {
        cudaFuncSetAttribute(k_gemm, cudaFuncAttributeMaxDynamicSharedMemorySize,
                             GSMEM_BYTES);
        attr_set = 1;
    }

    k_prep<<<(2 * t4 + 255) / 256, 256>>>(x, x0, w1, w2, n, t4);
    k_degree<<<eb, 256>>>(ei, e);
    k_scan<<<nb, 256>>>(n);
    k_fill<<<eb, 256>>>(ei, e);
    k_spmm<<<(n * 32 + 255) / 256, 256>>>(n, e);
    k_gemm<<<(n + BM - 1) / BM, 256, GSMEM_BYTES>>>(out, n);
}

// round 14
// speedup vs baseline: 1.2034x; 1.2034x over previous
#include <cuda_runtime.h>
#include <cuda_fp16.h>
#include <mma.h>
#include <cstdint>
#include <math.h>

using namespace nvcuda;

#define NMAX 100000
#define EMAX 800000
#define CDIM 128
#define KDIM 256

#define BETA_F 0.6931471805599453f
#define C1_F   0.15342640972002733f

// ---------------- scratch ----------------------------------------------------
__device__ int    g_count[NMAX];
__device__ float  g_dis[NMAX];
__device__ int    g_rowstart[NMAX];
__device__ int    g_cursor[NMAX];
__device__ int    g_csr[EMAX];
__device__ int    g_state[512];                // 0=invalid 1=aggregate 2=prefix
__device__ int    g_agg[512];
__device__ int    g_pre[512];
__device__ __half g_xh[(size_t)NMAX * CDIM];   // fp16 mirror of x (gather src)
__device__ __half g_x0h[(size_t)NMAX * CDIM];  // fp16 mirror of x0 (GEMM A)
__device__ __half g_hh[(size_t)NMAX * CDIM];   // h in fp16 (GEMM A)
__device__ __half g_bth[KDIM * CDIM];          // B' = beta*W + C1*[I;I], fp16

// ---------------- helpers ----------------------------------------------------
__device__ __forceinline__ uint32_t cvta_s(const void* p) {
    uint32_t a;
    asm("{ .reg .u64 t; cvta.to.shared.u64 t, %1; cvt.u32.u64 %0, t; }"
        : "=r"(a) : "l"(p));
    return a;
}

__device__ __forceinline__ void cp_async16(uint32_t dst, const void* src,
                                           uint32_t src_bytes) {
    asm volatile("cp.async.ca.shared.global [%0], [%1], 16, %2;"
                 :: "r"(dst), "l"(src), "r"(src_bytes) : "memory");
}

__device__ __forceinline__ void acc_row(float4& acc, uint2 r, float w) {
    float2 f0 = __half22float2(*(__half2*)&r.x);
    float2 f1 = __half22float2(*(__half2*)&r.y);
    acc.x += w * f0.x;
    acc.y += w * f0.y;
    acc.z += w * f1.x;
    acc.w += w * f1.y;
}

// ---------------- prep (fused): counts/state zero + B' + fp16 mirrors --------
__global__ void k_prep(const float* __restrict__ x, const float* __restrict__ x0,
                       const float* __restrict__ w1, const float* __restrict__ w2,
                       int n, int t4) {
    int i = blockIdx.x * blockDim.x + threadIdx.x;
    if (i < n) g_count[i] = 0;
    if (i < 512) g_state[i] = 0;
    if (i < KDIM * CDIM) {
        int nn = i & 127;
        int kk = i >> 7;
        float v = (kk < 128) ? w1[kk * 128 + nn] : w2[(kk - 128) * 128 + nn];
        float b = BETA_F * v;
        if ((kk & 127) == nn) b += C1_F;         // fold C1*(h+x0) into GEMM
        g_bth[i] = __float2half(b);
    }
    const float* src;
    __half* dst;
    int idx;
    if (i < t4)          { src = x;  dst = g_xh;  idx = i; }
    else if (i < 2 * t4) { src = x0; dst = g_x0h; idx = i - t4; }
    else return;
    float4 v = ((const float4*)src)[idx];
    __half2 a = __floats2half2_rn(v.x, v.y);
    __half2 b = __floats2half2_rn(v.z, v.w);
    uint2 pk;
    pk.x = *(uint32_t*)&a;
    pk.y = *(uint32_t*)&b;
    ((uint2*)dst)[idx] = pk;
}

__global__ void k_degree(const int* __restrict__ ei, int e) {
    int i = blockIdx.x * blockDim.x + threadIdx.x;
    if (i < e) atomicAdd(&g_count[ei[e + i]], 1);
}

// ---------------- single-pass scan, WARP-PARALLEL lookback -------------------
__global__ void k_scan(int n) {
    __shared__ int sm[256];
    __shared__ int s_base;
    int t = threadIdx.x;
    int b = blockIdx.x;
    int i = b * 256 + t;
    int c = (i < n) ? g_count[i] : 0;
    if (i < n) g_dis[i] = rsqrtf((float)(c + 1));
    sm[t] = c;
    __syncthreads();
    for (int off = 1; off < 256; off <<= 1) {
        int v = (t >= off) ? sm[t - off] : 0;
        __syncthreads();
        sm[t] += v;
        __syncthreads();
    }
    int total = sm[255];

    if (t == 0 && b > 0) {           // publish aggregate early
        g_agg[b] = total;
        __threadfence();
        g_state[b] = 1;
    }
    if (t < 32) {
        if (b == 0) {
            if (t == 0) {
                g_pre[0] = total;
                __threadfence();
                g_state[0] = 2;
                s_base = 0;
            }
        } else {
            int base = 0;
            int p = b - 1;
            while (true) {
                int idx = p - t;                 // lane t looks at block idx
                int st = 0, val = 0;
                if (idx >= 0) {
                    do { st = *(volatile int*)&g_state[idx]; } while (st == 0);
                    __threadfence();
                    val = (st == 2) ? g_pre[idx] : g_agg[idx];
                }
                unsigned m2 = __ballot_sync(0xFFFFFFFF, idx >= 0 && st == 2);
                int L = m2 ? (__ffs(m2) - 1) : 32;   // nearest published prefix
                int contrib = (t <= L && idx >= 0) ? val : 0;
#pragma unroll
                for (int o = 16; o > 0; o >>= 1)
                    contrib += __shfl_down_sync(0xFFFFFFFF, contrib, o);
                contrib = __shfl_sync(0xFFFFFFFF, contrib, 0);
                base += contrib;
                if (m2) break;
                p -= 32;
            }
            if (t == 0) {
                g_pre[b] = base + total;
                __threadfence();
                g_state[b] = 2;
                s_base = base;
            }
        }
    }
    __syncthreads();
    if (i < n) {
        int excl = s_base + sm[t] - c;
        g_rowstart[i] = excl;
        g_cursor[i]   = excl;
    }
}

__global__ void k_fill(const int* __restrict__ ei, int e) {
    int i = blockIdx.x * blockDim.x + threadIdx.x;
    if (i < e) {
        int s = ei[i];
        int d = ei[e + i];
        int pos = atomicAdd(&g_cursor[d], 1);
        g_csr[pos] = s;
    }
}

// ---------------- gather SpMM (warp per node, fp16, MLP=4) — R12-proven ------
__global__ void k_spmm(int n, int e) {
    int warp = (blockIdx.x * blockDim.x + threadIdx.x) >> 5;
    if (warp >= n) return;
    int lane = threadIdx.x & 31;

    const uint2* xh = (const uint2*)g_xh;   // 8B per lane = 4 halfs

    float di = g_dis[warp];
    uint2 sr = xh[(size_t)warp * 32 + lane];
    float sn = di * di;
    float4 acc = make_float4(0.f, 0.f, 0.f, 0.f);
    acc_row(acc, sr, sn);                   // self-loop

    int j   = g_rowstart[warp];
    int end = (warp + 1 < n) ? g_rowstart[warp + 1] : e;

    for (; j + 4 <= end; j += 4) {
        int i0 = __ldg(&g_csr[j + 0]);
        int i1 = __ldg(&g_csr[j + 1]);
        int i2 = __ldg(&g_csr[j + 2]);
        int i3 = __ldg(&g_csr[j + 3]);
        float w0 = di * __ldg(&g_dis[i0]);
        float w1 = di * __ldg(&g_dis[i1]);
        float w2 = di * __ldg(&g_dis[i2]);
        float w3 = di * __ldg(&g_dis[i3]);
        uint2 r0 = xh[(size_t)i0 * 32 + lane];
        uint2 r1 = xh[(size_t)i1 * 32 + lane];
        uint2 r2 = xh[(size_t)i2 * 32 + lane];
        uint2 r3 = xh[(size_t)i3 * 32 + lane];
        acc_row(acc, r0, w0);
        acc_row(acc, r1, w1);
        acc_row(acc, r2, w2);
        acc_row(acc, r3, w3);
    }
    for (; j < end; ++j) {
        int s = __ldg(&g_csr[j]);
        float w = di * __ldg(&g_dis[s]);
        uint2 r = xh[(size_t)s * 32 + lane];
        acc_row(acc, r, w);
    }

    __half2 h0 = __floats2half2_rn(acc.x, acc.y);
    __half2 h1 = __floats2half2_rn(acc.z, acc.w);
    uint2 pk;
    pk.x = *(uint32_t*)&h0;
    pk.y = *(uint32_t*)&h1;
    ((uint2*)g_hh)[(size_t)warp * 32 + lane] = pk;
}

// ---------------- fp16 WMMA GEMM (m16n16k16), cp.async double-buffered -------
// out = relu( [h|x0] @ g_bth ),  [N,256]x[256,128]; C1 term folded into g_bth
#define BM 128
#define BN 128
#define BK 64
#define LDA 72      // halfs (144 B pitch)
#define LDB 136     // halfs (272 B pitch)
#define NT 4

#define STG_A (128 * 72 * 2)   // 18432 B
#define STG_B (64 * 136 * 2)   // 17408 B
#define STG   (STG_A + STG_B)  // 35840 B
#define GSMEM_BYTES (2 * STG)  // 71680 B (boundary-block C park reuses this)

__global__ __launch_bounds__(256)
void k_gemm(float* __restrict__ out, int n) {
    extern __shared__ char smemc[];
    uint32_t sbase = cvta_s(smemc);

    int tid  = threadIdx.x;
    int warp = tid >> 5;
    int bm   = blockIdx.x * BM;
    int wm   = (warp >> 1) * 32;      // 0,32,64,96
    int wn   = (warp & 1) * 64;       // 0,64

    int ar  = tid >> 3;               // 0..31
    int ac8 = (tid & 7) * 8;          // half offset 0..56

    wmma::fragment<wmma::accumulator, 16, 16, 16, float> c[2][4];
#pragma unroll
    for (int i = 0; i < 2; ++i)
#pragma unroll
        for (int jf = 0; jf < 4; ++jf) wmma::fill_fragment(c[i][jf], 0.0f);

    auto issue_stage = [&](int s, int kt) {
        uint32_t aB = sbase + s * STG;
        uint32_t bB = aB + STG_A;
        const __half* Ap = (kt < 2) ? g_hh : g_x0h;
        int k0 = (kt & 1) * 64;
#pragma unroll
        for (int q = 0; q < 4; ++q) {
            int r  = ar + 32 * q;
            int gi = bm + r;
            const __half* src = Ap + (size_t)gi * CDIM + k0 + ac8;
            cp_async16(aB + (uint32_t)(r * LDA + ac8) * 2, src,
                       (gi < n) ? 16u : 0u);
            int idx = tid + 256 * q;
            int kb  = idx >> 4;            // 0..63
            int bc8 = (idx & 15) * 8;      // 0..120
            const __half* bsrc = g_bth + (size_t)(kt * 64 + kb) * CDIM + bc8;
            cp_async16(bB + (uint32_t)(kb * LDB + bc8) * 2, bsrc, 16u);
        }
        asm volatile("cp.async.commit_group;" ::: "memory");
    };

    issue_stage(0, 0);

    // deliberately NOT unrolled (L0 I$; R4/R10-proven)
    for (int kt = 0; kt < NT; ++kt) {
        if (kt + 1 < NT) {
            issue_stage((kt + 1) & 1, kt + 1);
            asm volatile("cp.async.wait_group 1;" ::: "memory");
        } else {
            asm volatile("cp.async.wait_group 0;" ::: "memory");
        }
        __syncthreads();

        const __half* sA = (const __half*)(smemc + (kt & 1) * STG);
        const __half* sB = (const __half*)(smemc + (kt & 1) * STG + STG_A);

#pragma unroll
        for (int kk = 0; kk < BK; kk += 16) {
            wmma::fragment<wmma::matrix_a, 16, 16, 16, __half,
                           wmma::row_major> af[2];
            wmma::fragment<wmma::matrix_b, 16, 16, 16, __half,
                           wmma::row_major> bf[4];
#pragma unroll
            for (int i = 0; i < 2; ++i)
                wmma::load_matrix_sync(af[i], &sA[(wm + 16 * i) * LDA + kk], LDA);
#pragma unroll
            for (int jf = 0; jf < 4; ++jf)
                wmma::load_matrix_sync(bf[jf], &sB[kk * LDB + wn + 16 * jf], LDB);
#pragma unroll
            for (int i = 0; i < 2; ++i)
#pragma unroll
                for (int jf = 0; jf < 4; ++jf)
                    wmma::mma_sync(c[i][jf], af[i], bf[jf], c[i][jf]);
        }
        __syncthreads();
    }

    // fragment-level relu
#pragma unroll
    for (int i = 0; i < 2; ++i)
#pragma unroll
        for (int jf = 0; jf < 4; ++jf)
#pragma unroll
            for (int t = 0; t < c[i][jf].num_elements; ++t)
                c[i][jf].x[t] = fmaxf(c[i][jf].x[t], 0.f);

    if (bm + BM <= n) {
        // interior block: store fragments straight to gmem (no smem park)
#pragma unroll
        for (int i = 0; i < 2; ++i)
#pragma unroll
            for (int jf = 0; jf < 4; ++jf)
                wmma::store_matrix_sync(
                    out + (size_t)(bm + wm + 16 * i) * CDIM + wn + 16 * jf,
                    c[i][jf], CDIM, wmma::mem_row_major);
    } else {
        // boundary block: park in smem, masked store
        float* sC = (float*)smemc;
#pragma unroll
        for (int i = 0; i < 2; ++i)
#pragma unroll
            for (int jf = 0; jf < 4; ++jf)
                wmma::store_matrix_sync(&sC[(wm + 16 * i) * 128 + wn + 16 * jf],
                                        c[i][jf], 128, wmma::mem_row_major);
        __syncthreads();
        for (int idx = tid; idx < BM * 32; idx += 256) {
            int r  = idx >> 5;
            int c4 = (idx & 31) * 4;
            int gi = bm + r;
            if (gi < n) {
                float4 g = *(float4*)&sC[r * 128 + c4];
                *(float4*)(out + (size_t)gi * CDIM + c4) = g;
            }
        }
    }
}

// ---------------- launch -----------------------------------------------------
extern "C" void kernel_launch(void* const* d_in, const int* in_sizes, int n_in,
                              void* d_out, int out_size) {
    const float* x  = (const float*)d_in[0];
    const float* x0 = (const float*)d_in[1];
    const float* w1 = (const float*)d_in[2];
    const float* w2 = (const float*)d_in[3];
    const int*   ei = (const int*)d_in[4];
    float* out = (float*)d_out;

    int n = in_sizes[0] / CDIM;
    int e = in_sizes[4] / 2;
    int nb = (n + 255) / 256;
    int eb = (e + 255) / 256;
    int t4 = n * (CDIM / 4);          // float4 count per feature matrix

    static int attr_set = 0;
    if (!attr_set) {
        cudaFuncSetAttribute(k_gemm, cudaFuncAttributeMaxDynamicSharedMemorySize,
                             GSMEM_BYTES);
        attr_set = 1;
    }

    k_prep<<<(2 * t4 + 255) / 256, 256>>>(x, x0, w1, w2, n, t4);
    k_degree<<<eb, 256>>>(ei, e);
    k_scan<<<nb, 256>>>(n);
    k_fill<<<eb, 256>>>(ei, e);
    k_spmm<<<(n * 32 + 255) / 256, 256>>>(n, e);
    k_gemm<<<(n + BM - 1) / BM, 256, GSMEM_BYTES>>>(out, n);
}

// round 15
// speedup vs baseline: 1.2833x; 1.0664x over previous
#include <cuda_runtime.h>
#include <cuda_fp16.h>
#include <mma.h>
#include <cstdint>
#include <math.h>

using namespace nvcuda;

#define NMAX 100000
#define EMAX 800000
#define CDIM 128
#define KDIM 256

#define BETA_F 0.6931471805599453f
#define C1_F   0.15342640972002733f

// ---------------- scratch ----------------------------------------------------
__device__ int    g_count[NMAX];        // zero at start of every replay (see k_offsets)
__device__ float  g_dis[NMAX];
__device__ int    g_rowstart[NMAX];
__device__ int    g_cursor[NMAX];
__device__ int    g_csr[EMAX];
__device__ int    g_bsum[512];
__device__ int    g_bpre[512];
__device__ int    g_tick;
__device__ __half g_xh[(size_t)NMAX * CDIM];   // xs = dis[row]*x, fp16
__device__ __half g_x0h[(size_t)NMAX * CDIM];  // fp16 mirror of x0 (GEMM A)
__device__ __half g_hh[(size_t)NMAX * CDIM];   // h in fp16 (GEMM A)
__device__ __half g_bth[KDIM * CDIM];          // B' = beta*W + C1*[I;I], fp16

// ---------------- helpers ----------------------------------------------------
__device__ __forceinline__ uint32_t cvta_s(const void* p) {
    uint32_t a;
    asm("{ .reg .u64 t; cvta.to.shared.u64 t, %1; cvt.u32.u64 %0, t; }"
        : "=r"(a) : "l"(p));
    return a;
}

__device__ __forceinline__ void cp_async16(uint32_t dst, const void* src,
                                           uint32_t src_bytes) {
    asm volatile("cp.async.ca.shared.global [%0], [%1], 16, %2;"
                 :: "r"(dst), "l"(src), "r"(src_bytes) : "memory");
}

__device__ __forceinline__ void add_row(float4& acc, uint2 r) {
    float2 f0 = __half22float2(*(__half2*)&r.x);
    float2 f1 = __half22float2(*(__half2*)&r.y);
    acc.x += f0.x;
    acc.y += f0.y;
    acc.z += f1.x;
    acc.w += f1.y;
}

// ---------------- 1. degree --------------------------------------------------
__global__ void k_degree(const int* __restrict__ ei, int e) {
    int i = blockIdx.x * blockDim.x + threadIdx.x;
    if (i < e) atomicAdd(&g_count[ei[e + i]], 1);
}

// ---------------- 2. block sums + dis; last block scans ----------------------
__global__ void k_blockscan(int n, int nb) {
    __shared__ int sh[256];
    __shared__ int flag;
    __shared__ int sm[512];
    int t = threadIdx.x;
    int i = blockIdx.x * 256 + t;
    int c = (i < n) ? g_count[i] : 0;
    if (i < n) g_dis[i] = rsqrtf((float)(c + 1));
    sh[t] = c;
    __syncthreads();
#pragma unroll
    for (int off = 128; off > 0; off >>= 1) {
        if (t < off) sh[t] += sh[t + off];
        __syncthreads();
    }
    if (t == 0) {
        g_bsum[blockIdx.x] = sh[0];
        __threadfence();
        int old = atomicAdd(&g_tick, 1);
        flag = (old == nb - 1);
    }
    __syncthreads();
    if (flag) {
        __threadfence();
        sm[t]       = (t < nb)       ? g_bsum[t]       : 0;
        sm[t + 256] = (t + 256 < nb) ? g_bsum[t + 256] : 0;
        __syncthreads();
        for (int off = 1; off < 512; off <<= 1) {
            int a = (t >= off) ? sm[t - off] : 0;
            int b = (t + 256 >= off) ? sm[t + 256 - off] : 0;
            __syncthreads();
            sm[t] += a;
            sm[t + 256] += b;
            __syncthreads();
        }
        if (t < nb)       g_bpre[t]       = (t > 0) ? sm[t - 1] : 0;
        if (t + 256 < nb) g_bpre[t + 256] = sm[t + 255];
        if (t == 0) g_tick = 0;
    }
}

// ---------------- 3. offsets (zeroes g_count for next replay) ----------------
__global__ void k_offsets(int n) {
    __shared__ int sm[256];
    int t = threadIdx.x;
    int i = blockIdx.x * 256 + t;
    int c = (i < n) ? g_count[i] : 0;
    sm[t] = c;
    __syncthreads();
    for (int off = 1; off < 256; off <<= 1) {
        int v = (t >= off) ? sm[t - off] : 0;
        __syncthreads();
        sm[t] += v;
        __syncthreads();
    }
    if (i < n) {
        int excl = sm[t] - c + g_bpre[blockIdx.x];
        g_rowstart[i] = excl;
        g_cursor[i]   = excl;
        g_count[i]    = 0;          // ready for next graph replay
    }
}

// ---------------- 4. fill CSR ------------------------------------------------
__global__ void k_fill(const int* __restrict__ ei, int e) {
    int i = blockIdx.x * blockDim.x + threadIdx.x;
    if (i < e) {
        int s = ei[i];
        int d = ei[e + i];
        int pos = atomicAdd(&g_cursor[d], 1);
        g_csr[pos] = s;
    }
}

// ---------------- 5. prep (AFTER scan): B' + scaled-x + x0 mirrors -----------
__global__ void k_prep(const float* __restrict__ x, const float* __restrict__ x0,
                       const float* __restrict__ w1, const float* __restrict__ w2,
                       int t4) {
    int i = blockIdx.x * blockDim.x + threadIdx.x;
    if (i < KDIM * CDIM) {
        int nn = i & 127;
        int kk = i >> 7;
        float v = (kk < 128) ? w1[kk * 128 + nn] : w2[(kk - 128) * 128 + nn];
        float b = BETA_F * v;
        if ((kk & 127) == nn) b += C1_F;         // fold C1*(h+x0) into GEMM
        g_bth[i] = __float2half(b);
    }
    if (i < t4) {                                 // xs = dis[row] * x  (fp16)
        float4 v = ((const float4*)x)[i];
        float d = g_dis[i >> 5];                  // 32 float4 per row
        __half2 a = __floats2half2_rn(d * v.x, d * v.y);
        __half2 b = __floats2half2_rn(d * v.z, d * v.w);
        uint2 pk;
        pk.x = *(uint32_t*)&a;
        pk.y = *(uint32_t*)&b;
        ((uint2*)g_xh)[i] = pk;
    } else if (i < 2 * t4) {                      // x0 mirror, unscaled
        int idx = i - t4;
        float4 v = ((const float4*)x0)[idx];
        __half2 a = __floats2half2_rn(v.x, v.y);
        __half2 b = __floats2half2_rn(v.z, v.w);
        uint2 pk;
        pk.x = *(uint32_t*)&a;
        pk.y = *(uint32_t*)&b;
        ((uint2*)g_x0h)[idx] = pk;
    }
}

// ---------------- 6. gather SpMM: pure add inner loop ------------------------
// h[d] = dis[d] * ( sum_src xs[src] + xs[d] )
__global__ void k_spmm(int n, int e) {
    int warp = (blockIdx.x * blockDim.x + threadIdx.x) >> 5;
    if (warp >= n) return;
    int lane = threadIdx.x & 31;

    const uint2* xh = (const uint2*)g_xh;   // 8B per lane = 4 halfs

    float di = g_dis[warp];
    float4 acc = make_float4(0.f, 0.f, 0.f, 0.f);
    add_row(acc, xh[(size_t)warp * 32 + lane]);   // self-loop (xs_dst)

    int j   = g_rowstart[warp];
    int end = (warp + 1 < n) ? g_rowstart[warp + 1] : e;

    for (; j + 4 <= end; j += 4) {
        int i0 = __ldg(&g_csr[j + 0]);
        int i1 = __ldg(&g_csr[j + 1]);
        int i2 = __ldg(&g_csr[j + 2]);
        int i3 = __ldg(&g_csr[j + 3]);
        uint2 r0 = xh[(size_t)i0 * 32 + lane];
        uint2 r1 = xh[(size_t)i1 * 32 + lane];
        uint2 r2 = xh[(size_t)i2 * 32 + lane];
        uint2 r3 = xh[(size_t)i3 * 32 + lane];
        add_row(acc, r0);
        add_row(acc, r1);
        add_row(acc, r2);
        add_row(acc, r3);
    }
    for (; j < end; ++j) {
        int s = __ldg(&g_csr[j]);
        add_row(acc, xh[(size_t)s * 32 + lane]);
    }

    __half2 h0 = __floats2half2_rn(di * acc.x, di * acc.y);
    __half2 h1 = __floats2half2_rn(di * acc.z, di * acc.w);
    uint2 pk;
    pk.x = *(uint32_t*)&h0;
    pk.y = *(uint32_t*)&h1;
    ((uint2*)g_hh)[(size_t)warp * 32 + lane] = pk;
}

// ---------------- 7. fp16 WMMA GEMM (m16n16k16), cp.async double-buffered ----
// out = relu( [h|x0] @ g_bth ),  [N,256]x[256,128]; C1 term folded into g_bth
#define BM 128
#define BN 128
#define BK 64
#define LDA 72      // halfs (144 B pitch)
#define LDB 136     // halfs (272 B pitch)
#define NT 4

#define STG_A (128 * 72 * 2)   // 18432 B
#define STG_B (64 * 136 * 2)   // 17408 B
#define STG   (STG_A + STG_B)  // 35840 B
#define GSMEM_BYTES (2 * STG)  // 71680 B (boundary-block C park reuses this)

__global__ __launch_bounds__(256)
void k_gemm(float* __restrict__ out, int n) {
    extern __shared__ char smemc[];
    uint32_t sbase = cvta_s(smemc);

    int tid  = threadIdx.x;
    int warp = tid >> 5;
    int bm   = blockIdx.x * BM;
    int wm   = (warp >> 1) * 32;      // 0,32,64,96
    int wn   = (warp & 1) * 64;       // 0,64

    int ar  = tid >> 3;               // 0..31
    int ac8 = (tid & 7) * 8;          // half offset 0..56

    wmma::fragment<wmma::accumulator, 16, 16, 16, float> c[2][4];
#pragma unroll
    for (int i = 0; i < 2; ++i)
#pragma unroll
        for (int jf = 0; jf < 4; ++jf) wmma::fill_fragment(c[i][jf], 0.0f);

    auto issue_stage = [&](int s, int kt) {
        uint32_t aB = sbase + s * STG;
        uint32_t bB = aB + STG_A;
        const __half* Ap = (kt < 2) ? g_hh : g_x0h;
        int k0 = (kt & 1) * 64;
#pragma unroll
        for (int q = 0; q < 4; ++q) {
            int r  = ar + 32 * q;
            int gi = bm + r;
            const __half* src = Ap + (size_t)gi * CDIM + k0 + ac8;
            cp_async16(aB + (uint32_t)(r * LDA + ac8) * 2, src,
                       (gi < n) ? 16u : 0u);
            int idx = tid + 256 * q;
            int kb  = idx >> 4;            // 0..63
            int bc8 = (idx & 15) * 8;      // 0..120
            const __half* bsrc = g_bth + (size_t)(kt * 64 + kb) * CDIM + bc8;
            cp_async16(bB + (uint32_t)(kb * LDB + bc8) * 2, bsrc, 16u);
        }
        asm volatile("cp.async.commit_group;" ::: "memory");
    };

    issue_stage(0, 0);

    // deliberately NOT unrolled (L0 I$; R4/R10-proven)
    for (int kt = 0; kt < NT; ++kt) {
        if (kt + 1 < NT) {
            issue_stage((kt + 1) & 1, kt + 1);
            asm volatile("cp.async.wait_group 1;" ::: "memory");
        } else {
            asm volatile("cp.async.wait_group 0;" ::: "memory");
        }
        __syncthreads();

        const __half* sA = (const __half*)(smemc + (kt & 1) * STG);
        const __half* sB = (const __half*)(smemc + (kt & 1) * STG + STG_A);

#pragma unroll
        for (int kk = 0; kk < BK; kk += 16) {
            wmma::fragment<wmma::matrix_a, 16, 16, 16, __half,
                           wmma::row_major> af[2];
            wmma::fragment<wmma::matrix_b, 16, 16, 16, __half,
                           wmma::row_major> bf[4];
#pragma unroll
            for (int i = 0; i < 2; ++i)
                wmma::load_matrix_sync(af[i], &sA[(wm + 16 * i) * LDA + kk], LDA);
#pragma unroll
            for (int jf = 0; jf < 4; ++jf)
                wmma::load_matrix_sync(bf[jf], &sB[kk * LDB + wn + 16 * jf], LDB);
#pragma unroll
            for (int i = 0; i < 2; ++i)
#pragma unroll
                for (int jf = 0; jf < 4; ++jf)
                    wmma::mma_sync(c[i][jf], af[i], bf[jf], c[i][jf]);
        }
        __syncthreads();
    }

    // fragment-level relu
#pragma unroll
    for (int i = 0; i < 2; ++i)
#pragma unroll
        for (int jf = 0; jf < 4; ++jf)
#pragma unroll
            for (int t = 0; t < c[i][jf].num_elements; ++t)
                c[i][jf].x[t] = fmaxf(c[i][jf].x[t], 0.f);

    if (bm + BM <= n) {
        // interior block: store fragments straight to gmem (no smem park)
#pragma unroll
        for (int i = 0; i < 2; ++i)
#pragma unroll
            for (int jf = 0; jf < 4; ++jf)
                wmma::store_matrix_sync(
                    out + (size_t)(bm + wm + 16 * i) * CDIM + wn + 16 * jf,
                    c[i][jf], CDIM, wmma::mem_row_major);
    } else {
        // boundary block: park in smem, masked store
        float* sC = (float*)smemc;
#pragma unroll
        for (int i = 0; i < 2; ++i)
#pragma unroll
            for (int jf = 0; jf < 4; ++jf)
                wmma::store_matrix_sync(&sC[(wm + 16 * i) * 128 + wn + 16 * jf],
                                        c[i][jf], 128, wmma::mem_row_major);
        __syncthreads();
        for (int idx = tid; idx < BM * 32; idx += 256) {
            int r  = idx >> 5;
            int c4 = (idx & 31) * 4;
            int gi = bm + r;
            if (gi < n) {
                float4 g = *(float4*)&sC[r * 128 + c4];
                *(float4*)(out + (size_t)gi * CDIM + c4) = g;
            }
        }
    }
}

// ---------------- launch -----------------------------------------------------
extern "C" void kernel_launch(void* const* d_in, const int* in_sizes, int n_in,
                              void* d_out, int out_size) {
    const float* x  = (const float*)d_in[0];
    const float* x0 = (const float*)d_in[1];
    const float* w1 = (const float*)d_in[2];
    const float* w2 = (const float*)d_in[3];
    const int*   ei = (const int*)d_in[4];
    float* out = (float*)d_out;

    int n = in_sizes[0] / CDIM;
    int e = in_sizes[4] / 2;
    int nb = (n + 255) / 256;
    int eb = (e + 255) / 256;
    int t4 = n * (CDIM / 4);          // float4 count per feature matrix

    static int attr_set = 0;
    if (!attr_set) {
        cudaFuncSetAttribute(k_gemm, cudaFuncAttributeMaxDynamicSharedMemorySize,
                             GSMEM_BYTES);
        attr_set = 1;
    }

    k_degree<<<eb, 256>>>(ei, e);
    k_blockscan<<<nb, 256>>>(n, nb);
    k_offsets<<<nb, 256>>>(n);
    k_fill<<<eb, 256>>>(ei, e);
    k_prep<<<(2 * t4 + 255) / 256, 256>>>(x, x0, w1, w2, t4);
    k_spmm<<<(n * 32 + 255) / 256, 256>>>(n, e);
    k_gemm<<<(n + BM - 1) / BM, 256, GSMEM_BYTES>>>(out, n);
}

// round 17
// speedup vs baseline: 1.3509x; 1.0526x over previous
#include <cuda_runtime.h>
#include <cuda_fp16.h>
#include <mma.h>
#include <cstdint>
#include <math.h>

using namespace nvcuda;

#define NMAX 100000
#define EMAX 800000
#define CDIM 128
#define KDIM 256

#define BETA_F 0.6931471805599453f
#define C1_F   0.15342640972002733f

// ---------------- scratch ----------------------------------------------------
__device__ int    g_count[NMAX];        // re-zeroed by k_offsets each replay
__device__ float  g_dis[NMAX];
__device__ int    g_rowstart[NMAX];
__device__ int    g_cursor[NMAX];
__device__ int    g_csr[EMAX];
__device__ int    g_bsum[512];
__device__ int    g_bpre[512];
__device__ int    g_tick;
__device__ __half g_xh[(size_t)NMAX * CDIM];   // xs = dis[row]*x, fp16
__device__ __half g_x0h[(size_t)NMAX * CDIM];  // fp16 mirror of x0 (GEMM A)
__device__ __half g_hh[(size_t)NMAX * CDIM];   // h in fp16 (GEMM A)
__device__ __half g_bth[KDIM * CDIM];          // B' = beta*W + C1*[I;I], fp16

// ---------------- helpers ----------------------------------------------------
__device__ __forceinline__ uint32_t cvta_s(const void* p) {
    uint32_t a;
    asm("{ .reg .u64 t; cvta.to.shared.u64 t, %1; cvt.u32.u64 %0, t; }"
        : "=r"(a) : "l"(p));
    return a;
}

__device__ __forceinline__ void cp_async16(uint32_t dst, const void* src,
                                           uint32_t src_bytes) {
    asm volatile("cp.async.ca.shared.global [%0], [%1], 16, %2;"
                 :: "r"(dst), "l"(src), "r"(src_bytes) : "memory");
}

__device__ __forceinline__ void add_row(float4& acc, uint2 r) {
    float2 f0 = __half22float2(*(__half2*)&r.x);
    float2 f1 = __half22float2(*(__half2*)&r.y);
    acc.x += f0.x;
    acc.y += f0.y;
    acc.z += f1.x;
    acc.w += f1.y;
}

// ---------------- stream-A chain ---------------------------------------------
__global__ void k_degree(const int* __restrict__ ei, int e) {
    int i = blockIdx.x * blockDim.x + threadIdx.x;
    if (i < e) atomicAdd(&g_count[ei[e + i]], 1);
}

__global__ void k_blockscan(int n, int nb) {
    __shared__ int sh[256];
    __shared__ int flag;
    __shared__ int sm[512];
    int t = threadIdx.x;
    int i = blockIdx.x * 256 + t;
    int c = (i < n) ? g_count[i] : 0;
    if (i < n) g_dis[i] = rsqrtf((float)(c + 1));
    sh[t] = c;
    __syncthreads();
#pragma unroll
    for (int off = 128; off > 0; off >>= 1) {
        if (t < off) sh[t] += sh[t + off];
        __syncthreads();
    }
    if (t == 0) {
        g_bsum[blockIdx.x] = sh[0];
        __threadfence();
        int old = atomicAdd(&g_tick, 1);
        flag = (old == nb - 1);
    }
    __syncthreads();
    if (flag) {
        __threadfence();
        sm[t]       = (t < nb)       ? g_bsum[t]       : 0;
        sm[t + 256] = (t + 256 < nb) ? g_bsum[t + 256] : 0;
        __syncthreads();
        for (int off = 1; off < 512; off <<= 1) {
            int a = (t >= off) ? sm[t - off] : 0;
            int b = (t + 256 >= off) ? sm[t + 256 - off] : 0;
            __syncthreads();
            sm[t] += a;
            sm[t + 256] += b;
            __syncthreads();
        }
        if (t < nb)       g_bpre[t]       = (t > 0) ? sm[t - 1] : 0;
        if (t + 256 < nb) g_bpre[t + 256] = sm[t + 255];
        if (t == 0) g_tick = 0;
    }
}

__global__ void k_offsets(int n) {
    __shared__ int sm[256];
    int t = threadIdx.x;
    int i = blockIdx.x * 256 + t;
    int c = (i < n) ? g_count[i] : 0;
    sm[t] = c;
    __syncthreads();
    for (int off = 1; off < 256; off <<= 1) {
        int v = (t >= off) ? sm[t - off] : 0;
        __syncthreads();
        sm[t] += v;
        __syncthreads();
    }
    if (i < n) {
        int excl = sm[t] - c + g_bpre[blockIdx.x];
        g_rowstart[i] = excl;
        g_cursor[i]   = excl;
        g_count[i]    = 0;          // ready for next graph replay
    }
}

__global__ void k_fill(const int* __restrict__ ei, int e) {
    int i = blockIdx.x * blockDim.x + threadIdx.x;
    if (i < e) {
        int s = ei[i];
        int d = ei[e + i];
        int pos = atomicAdd(&g_cursor[d], 1);
        g_csr[pos] = s;
    }
}

// ---------------- stream-B kernels -------------------------------------------
// B' + x0 mirror: depends on nothing
__global__ void k_prepw(const float* __restrict__ x0,
                        const float* __restrict__ w1,
                        const float* __restrict__ w2, int t4) {
    int i = blockIdx.x * blockDim.x + threadIdx.x;
    if (i < KDIM * CDIM) {
        int nn = i & 127;
        int kk = i >> 7;
        float v = (kk < 128) ? w1[kk * 128 + nn] : w2[(kk - 128) * 128 + nn];
        float b = BETA_F * v;
        if ((kk & 127) == nn) b += C1_F;         // fold C1*(h+x0) into GEMM
        g_bth[i] = __float2half(b);
    }
    if (i < t4) {
        float4 v = ((const float4*)x0)[i];
        __half2 a = __floats2half2_rn(v.x, v.y);
        __half2 b = __floats2half2_rn(v.z, v.w);
        uint2 pk;
        pk.x = *(uint32_t*)&a;
        pk.y = *(uint32_t*)&b;
        ((uint2*)g_x0h)[i] = pk;
    }
}

// xs = dis[row]*x: depends on blockscan (dis)
__global__ void k_prepx(const float* __restrict__ x, int t4) {
    int i = blockIdx.x * blockDim.x + threadIdx.x;
    if (i < t4) {
        float4 v = ((const float4*)x)[i];
        float d = g_dis[i >> 5];                  // 32 float4 per row
        __half2 a = __floats2half2_rn(d * v.x, d * v.y);
        __half2 b = __floats2half2_rn(d * v.z, d * v.w);
        uint2 pk;
        pk.x = *(uint32_t*)&a;
        pk.y = *(uint32_t*)&b;
        ((uint2*)g_xh)[i] = pk;
    }
}

// ---------------- gather SpMM: pure add inner loop ---------------------------
// h[d] = dis[d] * ( sum_src xs[src] + xs[d] )
__global__ void k_spmm(int n, int e) {
    int warp = (blockIdx.x * blockDim.x + threadIdx.x) >> 5;
    if (warp >= n) return;
    int lane = threadIdx.x & 31;

    const uint2* xh = (const uint2*)g_xh;   // 8B per lane = 4 halfs

    float di = g_dis[warp];
    float4 acc = make_float4(0.f, 0.f, 0.f, 0.f);
    add_row(acc, xh[(size_t)warp * 32 + lane]);   // self-loop (xs_dst)

    int j   = g_rowstart[warp];
    int end = (warp + 1 < n) ? g_rowstart[warp + 1] : e;

    for (; j + 4 <= end; j += 4) {
        int i0 = __ldg(&g_csr[j + 0]);
        int i1 = __ldg(&g_csr[j + 1]);
        int i2 = __ldg(&g_csr[j + 2]);
        int i3 = __ldg(&g_csr[j + 3]);
        uint2 r0 = xh[(size_t)i0 * 32 + lane];
        uint2 r1 = xh[(size_t)i1 * 32 + lane];
        uint2 r2 = xh[(size_t)i2 * 32 + lane];
        uint2 r3 = xh[(size_t)i3 * 32 + lane];
        add_row(acc, r0);
        add_row(acc, r1);
        add_row(acc, r2);
        add_row(acc, r3);
    }
    for (; j < end; ++j) {
        int s = __ldg(&g_csr[j]);
        add_row(acc, xh[(size_t)s * 32 + lane]);
    }

    __half2 h0 = __floats2half2_rn(di * acc.x, di * acc.y);
    __half2 h1 = __floats2half2_rn(di * acc.z, di * acc.w);
    uint2 pk;
    pk.x = *(uint32_t*)&h0;
    pk.y = *(uint32_t*)&h1;
    ((uint2*)g_hh)[(size_t)warp * 32 + lane] = pk;
}

// ---------------- fp16 WMMA GEMM (m16n16k16), cp.async double-buffered -------
// out = relu( [h|x0] @ g_bth ),  [N,256]x[256,128]; C1 term folded into g_bth
#define BM 128
#define BN 128
#define BK 64
#define LDA 72      // halfs (144 B pitch)
#define LDB 136     // halfs (272 B pitch)
#define NT 4

#define STG_A (128 * 72 * 2)   // 18432 B
#define STG_B (64 * 136 * 2)   // 17408 B
#define STG   (STG_A + STG_B)  // 35840 B
#define GSMEM_BYTES (2 * STG)  // 71680 B (boundary-block C park reuses this)

__global__ __launch_bounds__(256)
void k_gemm(float* __restrict__ out, int n) {
    extern __shared__ char smemc[];
    uint32_t sbase = cvta_s(smemc);

    int tid  = threadIdx.x;
    int warp = tid >> 5;
    int bm   = blockIdx.x * BM;
    int wm   = (warp >> 1) * 32;      // 0,32,64,96
    int wn   = (warp & 1) * 64;       // 0,64

    int ar  = tid >> 3;               // 0..31
    int ac8 = (tid & 7) * 8;          // half offset 0..56

    wmma::fragment<wmma::accumulator, 16, 16, 16, float> c[2][4];
#pragma unroll
    for (int i = 0; i < 2; ++i)
#pragma unroll
        for (int jf = 0; jf < 4; ++jf) wmma::fill_fragment(c[i][jf], 0.0f);

    auto issue_stage = [&](int s, int kt) {
        uint32_t aB = sbase + s * STG;
        uint32_t bB = aB + STG_A;
        const __half* Ap = (kt < 2) ? g_hh : g_x0h;
        int k0 = (kt & 1) * 64;
#pragma unroll
        for (int q = 0; q < 4; ++q) {
            int r  = ar + 32 * q;
            int gi = bm + r;
            const __half* src = Ap + (size_t)gi * CDIM + k0 + ac8;
            cp_async16(aB + (uint32_t)(r * LDA + ac8) * 2, src,
                       (gi < n) ? 16u : 0u);
            int idx = tid + 256 * q;
            int kb  = idx >> 4;            // 0..63
            int bc8 = (idx & 15) * 8;      // 0..120
            const __half* bsrc = g_bth + (size_t)(kt * 64 + kb) * CDIM + bc8;
            cp_async16(bB + (uint32_t)(kb * LDB + bc8) * 2, bsrc, 16u);
        }
        asm volatile("cp.async.commit_group;" ::: "memory");
    };

    issue_stage(0, 0);

    // deliberately NOT unrolled (L0 I$; R4/R10-proven)
    for (int kt = 0; kt < NT; ++kt) {
        if (kt + 1 < NT) {
            issue_stage((kt + 1) & 1, kt + 1);
            asm volatile("cp.async.wait_group 1;" ::: "memory");
        } else {
            asm volatile("cp.async.wait_group 0;" ::: "memory");
        }
        __syncthreads();

        const __half* sA = (const __half*)(smemc + (kt & 1) * STG);
        const __half* sB = (const __half*)(smemc + (kt & 1) * STG + STG_A);

#pragma unroll
        for (int kk = 0; kk < BK; kk += 16) {
            wmma::fragment<wmma::matrix_a, 16, 16, 16, __half,
                           wmma::row_major> af[2];
            wmma::fragment<wmma::matrix_b, 16, 16, 16, __half,
                           wmma::row_major> bf[4];
#pragma unroll
            for (int i = 0; i < 2; ++i)
                wmma::load_matrix_sync(af[i], &sA[(wm + 16 * i) * LDA + kk], LDA);
#pragma unroll
            for (int jf = 0; jf < 4; ++jf)
                wmma::load_matrix_sync(bf[jf], &sB[kk * LDB + wn + 16 * jf], LDB);
#pragma unroll
            for (int i = 0; i < 2; ++i)
#pragma unroll
                for (int jf = 0; jf < 4; ++jf)
                    wmma::mma_sync(c[i][jf], af[i], bf[jf], c[i][jf]);
        }
        __syncthreads();
    }

    // fragment-level relu
#pragma unroll
    for (int i = 0; i < 2; ++i)
#pragma unroll
        for (int jf = 0; jf < 4; ++jf)
#pragma unroll
            for (int t = 0; t < c[i][jf].num_elements; ++t)
                c[i][jf].x[t] = fmaxf(c[i][jf].x[t], 0.f);

    if (bm + BM <= n) {
        // interior block: store fragments straight to gmem (no smem park)
#pragma unroll
        for (int i = 0; i < 2; ++i)
#pragma unroll
            for (int jf = 0; jf < 4; ++jf)
                wmma::store_matrix_sync(
                    out + (size_t)(bm + wm + 16 * i) * CDIM + wn + 16 * jf,
                    c[i][jf], CDIM, wmma::mem_row_major);
    } else {
        // boundary block: park in smem, masked store
        float* sC = (float*)smemc;
#pragma unroll
        for (int i = 0; i < 2; ++i)
#pragma unroll
            for (int jf = 0; jf < 4; ++jf)
                wmma::store_matrix_sync(&sC[(wm + 16 * i) * 128 + wn + 16 * jf],
                                        c[i][jf], 128, wmma::mem_row_major);
        __syncthreads();
        for (int idx = tid; idx < BM * 32; idx += 256) {
            int r  = idx >> 5;
            int c4 = (idx & 31) * 4;
            int gi = bm + r;
            if (gi < n) {
                float4 g = *(float4*)&sC[r * 128 + c4];
                *(float4*)(out + (size_t)gi * CDIM + c4) = g;
            }
        }
    }
}

// ---------------- launch: two-stream fork/join (graph-capturable) ------------
extern "C" void kernel_launch(void* const* d_in, const int* in_sizes, int n_in,
                              void* d_out, int out_size) {
    const float* x  = (const float*)d_in[0];
    const float* x0 = (const float*)d_in[1];
    const float* w1 = (const float*)d_in[2];
    const float* w2 = (const float*)d_in[3];
    const int*   ei = (const int*)d_in[4];
    float* out = (float*)d_out;

    int n = in_sizes[0] / CDIM;
    int e = in_sizes[4] / 2;
    int nb = (n + 255) / 256;
    int eb = (e + 255) / 256;
    int t4 = n * (CDIM / 4);          // float4 count per feature matrix

    static cudaStream_t s1 = nullptr;
    static cudaEvent_t evFork, evDis, evJoin;
    if (!s1) {                        // first (uncaptured) correctness call
        cudaStreamCreateWithFlags(&s1, cudaStreamNonBlocking);
        cudaEventCreateWithFlags(&evFork, cudaEventDisableTiming);
        cudaEventCreateWithFlags(&evDis,  cudaEventDisableTiming);
        cudaEventCreateWithFlags(&evJoin, cudaEventDisableTiming);
        cudaFuncSetAttribute(k_gemm, cudaFuncAttributeMaxDynamicSharedMemorySize,
                             GSMEM_BYTES);
    }

    // fork: B'/x0 mirror on s1, CSR chain on the main stream
    cudaEventRecord(evFork, 0);
    cudaStreamWaitEvent(s1, evFork, 0);
    k_prepw<<<(t4 + 255) / 256, 256, 0, s1>>>(x0, w1, w2, t4);

    k_degree<<<eb, 256>>>(ei, e);
    k_blockscan<<<nb, 256>>>(n, nb);

    // dis ready -> x scaling on s1, overlapping offsets+fill
    cudaEventRecord(evDis, 0);
    cudaStreamWaitEvent(s1, evDis, 0);
    k_prepx<<<(t4 + 255) / 256, 256, 0, s1>>>(x, t4);

    k_offsets<<<nb, 256>>>(n);
    k_fill<<<eb, 256>>>(ei, e);

    // join before spmm (needs g_xh); gemm deps (g_x0h/g_bth) are upstream
    cudaEventRecord(evJoin, s1);
    cudaStreamWaitEvent(0, evJoin, 0);

    k_spmm<<<(n * 32 + 255) / 256, 256>>>(n, e);
    k_gemm<<<(n + BM - 1) / BM, 256, GSMEM_BYTES>>>(out, n);
}